// round 6
// baseline (speedup 1.0000x reference)
#include <cuda_runtime.h>
#include <cstdint>

#define T_SEQ 2048
#define NB    64
#define DIN   256
#define NH    256

// scratch: precomputed input projection xw[t][b][h]  (128 MB, static — no allocs)
__device__ float g_xw[(size_t)T_SEQ * NB * NH];

// padded local-h index: stride 40 words per 32-float window -> the 4 windows
// start at banks 0/8/16/24 (distinct quads) => conflict-free broadcast LDS.128
#define PHYS32(k) ((k) + (((k) >> 5) << 3))
#define HLOC 152   // 3*40 + 32

// ---------------- packed fp32x2 helpers (sm_100+) ----------------
__device__ __forceinline__ unsigned long long fma2(unsigned long long a,
                                                   unsigned long long b,
                                                   unsigned long long c) {
    unsigned long long d;
    asm("fma.rn.f32x2 %0, %1, %2, %3;" : "=l"(d) : "l"(a), "l"(b), "l"(c));
    return d;
}
__device__ __forceinline__ float f2sum(unsigned long long v) {
    float lo, hi;
    asm("mov.b64 {%0, %1}, %2;" : "=f"(lo), "=f"(hi) : "l"(v));
    return lo + hi;
}
__device__ __forceinline__ unsigned long long packf2(float lo, float hi) {
    unsigned long long r;
    asm("mov.b64 %0, {%1, %2};" : "=l"(r) : "f"(lo), "f"(hi));
    return r;
}
__device__ __forceinline__ uint32_t smem_u32(const void* p) {
    uint32_t a;
    asm("{ .reg .u64 t; cvta.to.shared.u64 t, %1; cvt.u32.u64 %0, t; }"
        : "=r"(a) : "l"(p));
    return a;
}
__device__ __forceinline__ uint32_t mapa_(uint32_t addr, int rank) {
    uint32_t r;
    asm("mapa.shared::cluster.u32 %0, %1, %2;" : "=r"(r) : "r"(addr), "r"(rank));
    return r;
}
__device__ __forceinline__ void cluster_sync_() {
    asm volatile("barrier.cluster.arrive.aligned;\n\t"
                 "barrier.cluster.wait.aligned;" ::: "memory");
}
__device__ __forceinline__ void cluster_arrive_() {
    asm volatile("barrier.cluster.arrive.aligned;" ::: "memory");
}
__device__ __forceinline__ void cluster_wait_() {
    asm volatile("barrier.cluster.wait.aligned;" ::: "memory");
}
__device__ __forceinline__ void st_cluster_b64(uint32_t addr, unsigned long long v) {
    asm volatile("st.shared::cluster.b64 [%0], %1;" :: "r"(addr), "l"(v) : "memory");
}
__device__ __forceinline__ float tanh_fast(float x) {
    float e = __expf(2.0f * x);
    return 1.0f - __fdividef(2.0f, e + 1.0f);
}

// =================================================================
// Kernel 1: input projection  (unchanged — proven)
// =================================================================
__global__ void __launch_bounds__(256, 1)
xw_kernel(const float* __restrict__ x,
          const float* __restrict__ w_ih,
          const float* __restrict__ b_ih,
          const float* __restrict__ b_hh) {
    __shared__ __align__(16) float xs[8][256];
    __shared__ float pbuf[8 * 512];

    const int tid  = threadIdx.x;
    const int w    = tid >> 5;
    const int lane = tid & 31;
    const int kg   = w >> 1;
    const int og   = ((w & 1) << 5) | lane;
    const int half = blockIdx.y;
    const int rowbase0 = blockIdx.x * 128;

    unsigned long long wa[32], wb[32];
    {
        const int j0 = half * 128 + og, j1 = j0 + 64;
        const unsigned long long* p0 =
            (const unsigned long long*)(w_ih + (size_t)j0 * DIN + kg * 64);
        const unsigned long long* p1 =
            (const unsigned long long*)(w_ih + (size_t)j1 * DIN + kg * 64);
#pragma unroll
        for (int i = 0; i < 32; i++) { wa[i] = p0[i]; wb[i] = p1[i]; }
    }
    float bias = 0.f;
    if (tid < 128) bias = b_ih[half * 128 + tid] + b_hh[half * 128 + tid];

    const float4* xg = (const float4*)x;
    {
        int q = tid, r = q >> 6, c4 = q & 63;
        ((float4*)xs)[q]       = xg[(size_t)(rowbase0 + r) * 64 + c4];
        ((float4*)xs)[q + 256] = xg[(size_t)(rowbase0 + 4 + r) * 64 + c4];
    }
    __syncthreads();

    for (int it = 0; it < 16; it++) {
        const int rowbase = rowbase0 + it * 8;
        float4 n0, n1;
        if (it < 15) {
            int q = tid, r = q >> 6, c4 = q & 63;
            int nrb = rowbase + 8;
            n0 = xg[(size_t)(nrb + r) * 64 + c4];
            n1 = xg[(size_t)(nrb + 4 + r) * 64 + c4];
        }
        unsigned long long acc[8][2];
#pragma unroll
        for (int r = 0; r < 8; r++) { acc[r][0] = 0ull; acc[r][1] = 0ull; }
#pragma unroll
        for (int r = 0; r < 8; r++) {
            const ulonglong2* xp = (const ulonglong2*)&xs[r][kg * 64];
#pragma unroll
            for (int i = 0; i < 16; i++) {
                ulonglong2 hv = xp[i];
                acc[r][0] = fma2(wa[2 * i],     hv.x, acc[r][0]);
                acc[r][0] = fma2(wa[2 * i + 1], hv.y, acc[r][0]);
                acc[r][1] = fma2(wb[2 * i],     hv.x, acc[r][1]);
                acc[r][1] = fma2(wb[2 * i + 1], hv.y, acc[r][1]);
            }
        }
#pragma unroll
        for (int r = 0; r < 8; r++) {
            pbuf[r * 512 + kg * 128 + og]      = f2sum(acc[r][0]);
            pbuf[r * 512 + kg * 128 + og + 64] = f2sum(acc[r][1]);
        }
        __syncthreads();
        if (it < 15) {
            int q = tid;
            ((float4*)xs)[q]       = n0;
            ((float4*)xs)[q + 256] = n1;
        }
        if (tid < 128) {
#pragma unroll
            for (int r = 0; r < 8; r++) {
                float s = pbuf[r * 512 + tid] + pbuf[r * 512 + 128 + tid] +
                          pbuf[r * 512 + 256 + tid] + pbuf[r * 512 + 384 + tid] + bias;
                g_xw[(size_t)(rowbase + r) * NH + half * 128 + tid] = s;
            }
        }
        __syncthreads();
    }
}

// =================================================================
// Kernel 2: recurrence v6 — partial-sum exchange (h never crosses CTAs).
//   64 clusters x 2 CTAs x 256 thr. CTA c materializes h-half J_c=[128c,+128)
//   and holds w_hh[all j][K_c] (K_c = its own 128-k slice) in registers.
//   Thread (w,l): jg=l&7, kp=l>>3; rows j0=32w+4jg (4 rows), k-window
//   K_c[32kp..+32). Per step: FMA over LOCAL h-half only -> 2-level shfl
//   reduce -> push 4 partials for peer-half rows -> arrive -> wait ->
//   own-half writers add peer partials + xw, tanh, store h-half locally.
// =================================================================
__global__ void __launch_bounds__(256, 1) __cluster_dims__(2, 1, 1)
rnn_kernel(const float* __restrict__ w_hh, float* __restrict__ out) {
    __shared__ __align__(16) float hloc[2][HLOC];   // own h-half, padded, 2-buf
    __shared__ __align__(16) float pin[2][128];     // incoming peer partials

    const int tid  = threadIdx.x;
    const int w    = tid >> 5, l = tid & 31;
    const int jg   = l & 7,  kp = l >> 3;
    const int b    = blockIdx.x >> 1;
    const int c    = blockIdx.x & 1;
    const int peer = c ^ 1;
    const int j0   = 32 * w + 4 * jg;              // 4 rows of w_hh (global j)
    const bool own  = ((w >> 2) == c);             // warp's rows in own half?
    const bool wlan = own && (kp == 0);            // writer lanes (128 outputs)
    const bool plan = (!own) && (kp == 0);         // pusher lanes
    const int jl   = j0 & 127;                     // index within a 128-half

    // register-resident weights: rows j0..j0+3, k = c*128 + 32*kp + [0,32)
    unsigned long long wv[4][16];
#pragma unroll
    for (int jj = 0; jj < 4; jj++) {
        const unsigned long long* row = (const unsigned long long*)
            (w_hh + (size_t)(j0 + jj) * NH + c * 128 + kp * 32);
#pragma unroll
        for (int i = 0; i < 16; i++) wv[jj][i] = row[i];
    }

    for (int i = tid; i < 2 * HLOC; i += 256) ((float*)hloc)[i] = 0.f;  // h0=0

    // peer-side partial-buffer slots (for pusher lanes)
    const uint32_t prem[2] = { mapa_(smem_u32(&pin[0][jl]), peer),
                               mapa_(smem_u32(&pin[1][jl]), peer) };
    const int hoff = PHYS32(jl & 127);             // writer's h store offset

    cluster_sync_();                               // zeros visible cluster-wide

    float4 xc, x1, x2;
    if (wlan) {
        xc = *(const float4*)&g_xw[(size_t)b * NH + j0];
        x1 = *(const float4*)&g_xw[((size_t)NB + b) * NH + j0];
    }

    for (int s = 0; s < T_SEQ; s++) {
        const int p = s & 1, q = p ^ 1;

        // ---- FMA: 4 rows x 32 k, ALL from local h-half ----
        const ulonglong2* hp = (const ulonglong2*)&hloc[p][PHYS32(kp * 32)];
        unsigned long long a0 = 0ull, a1 = 0ull, a2 = 0ull, a3 = 0ull;
#pragma unroll
        for (int i = 0; i < 8; i++) {
            ulonglong2 hv = hp[i];
            a0 = fma2(wv[0][2 * i], hv.x, a0);
            a0 = fma2(wv[0][2 * i + 1], hv.y, a0);
            a1 = fma2(wv[1][2 * i], hv.x, a1);
            a1 = fma2(wv[1][2 * i + 1], hv.y, a1);
            a2 = fma2(wv[2][2 * i], hv.x, a2);
            a2 = fma2(wv[2][2 * i + 1], hv.y, a2);
            a3 = fma2(wv[3][2 * i], hv.x, a3);
            a3 = fma2(wv[3][2 * i + 1], hv.y, a3);
        }
        float v0 = f2sum(a0), v1 = f2sum(a1), v2 = f2sum(a2), v3 = f2sum(a3);
#pragma unroll
        for (int d = 8; d <= 16; d <<= 1) {        // butterfly over 4 k-parts
            v0 += __shfl_xor_sync(0xffffffffu, v0, d);
            v1 += __shfl_xor_sync(0xffffffffu, v1, d);
            v2 += __shfl_xor_sync(0xffffffffu, v2, d);
            v3 += __shfl_xor_sync(0xffffffffu, v3, d);
        }

        // ---- push partials for peer-owned rows, then release ----
        if (plan) {
            st_cluster_b64(prem[p],     packf2(v0, v1));
            st_cluster_b64(prem[p] + 8, packf2(v2, v3));
        }
        cluster_arrive_();

        // off-critical-path work between arrive and wait
        if (wlan && s + 2 < T_SEQ)
            x2 = *(const float4*)&g_xw[((size_t)(s + 2) * NB + b) * NH + j0];

        cluster_wait_();                           // peer partials visible

        if (wlan) {
            float4 pv = *(const float4*)&pin[p][jl];
            v0 = tanh_fast(v0 + pv.x + xc.x);
            v1 = tanh_fast(v1 + pv.y + xc.y);
            v2 = tanh_fast(v2 + pv.z + xc.z);
            v3 = tanh_fast(v3 + pv.w + xc.w);
            *(float4*)&hloc[q][hoff] = make_float4(v0, v1, v2, v3);  // local h
            *(float4*)(out + ((size_t)s * NB + b) * NH + j0) =
                make_float4(v0, v1, v2, v3);
            xc = x1; x1 = x2;
        }
        __syncthreads();                           // h(q) visible CTA-wide
    }
    cluster_sync_();   // keep smem alive for in-flight peer stores
}

// =================================================================
extern "C" void kernel_launch(void* const* d_in, const int* in_sizes, int n_in,
                              void* d_out, int out_size) {
    const float* x    = (const float*)d_in[0];
    const float* w_ih = (const float*)d_in[1];
    const float* w_hh = (const float*)d_in[2];
    const float* b_ih = (const float*)d_in[3];
    const float* b_hh = (const float*)d_in[4];
    float* out = (float*)d_out;

    dim3 g1(1024, 2);
    xw_kernel<<<g1, 256>>>(x, w_ih, b_ih, b_hh);
    rnn_kernel<<<128, 256>>>(w_hh, out);
}